// round 12
// baseline (speedup 1.0000x reference)
#include <cuda_runtime.h>

// R12: tail-granularity tune. 2048 CTAs x 128 thr (4 warps = 1 tile per CTA).
// Hot loop identical to R8 (roofed at ~6.25 TB/s); finer CTA retire granularity
// to shrink end-of-kernel drain stagger.
#define NUM_TILES 2048
__device__ float g_tile_sums[NUM_TILES];   // per-tile |sum|
__device__ unsigned int g_done_count = 0;

__global__ void __launch_bounds__(128, 14) lthu_kernel(
    const float* __restrict__ fake, const float* __restrict__ real,
    float* __restrict__ out)
{
    __shared__ float slice_sums[4];   // one per warp
    __shared__ bool is_last;

    const int lane = threadIdx.x & 31;
    const int wid  = threadIdx.x >> 5;     // 0..3
    const int tile = blockIdx.x;            // 0..2047, one tile per CTA
    const int q    = wid;                   // row group q*32 .. q*32+31

    const int b   = tile >> 6;              // image (64 tiles per image)
    const int rem = tile & 63;
    const int by  = rem >> 3;
    const int bx  = rem & 7;
    const long base = (long)b * (1024 * 1024)
                    + (long)(by * 128 + q * 32) * 1024
                    + (long)bx * 128;

    const float4* f4 = (const float4*)(fake + base) + lane;
    const float4* r4 = (const float4*)(real + base) + lane;
    // slice: 32 rows x 32 float4/row; row stride in float4 units = 256

    float acc = 0.0f;
    #pragma unroll 16
    for (int r = 0; r < 32; ++r) {
        float4 fv = f4[r * 256];
        float4 rv = r4[r * 256];
        acc += (fv.x - rv.x) + (fv.y - rv.y) + (fv.z - rv.z) + (fv.w - rv.w);
    }

    // warp-local reduce — no CTA barrier while other warps stream
    #pragma unroll
    for (int off = 16; off > 0; off >>= 1)
        acc += __shfl_xor_sync(0xFFFFFFFFu, acc, off);

    if (lane == 0)
        slice_sums[wid] = acc;

    __syncthreads();   // single barrier, after all loads complete

    if (threadIdx.x == 0) {
        float t = (slice_sums[0] + slice_sums[1]) + (slice_sums[2] + slice_sums[3]);
        g_tile_sums[tile] = fabsf(t);
        __threadfence();
        unsigned int prev = atomicAdd(&g_done_count, 1u);
        is_last = (prev == NUM_TILES - 1);
    }
    __syncthreads();

    if (is_last) {
        // fixed-order deterministic reduce of 2048 per-tile sums (128 thr)
        float s = 0.0f;
        #pragma unroll
        for (int it = 0; it < 16; ++it)
            s += g_tile_sums[threadIdx.x + it * 128];

        #pragma unroll
        for (int off = 16; off > 0; off >>= 1)
            s += __shfl_xor_sync(0xFFFFFFFFu, s, off);

        __shared__ float warp_sums[4];
        if (lane == 0) warp_sums[wid] = s;
        __syncthreads();
        if (threadIdx.x == 0) {
            float v = (warp_sums[0] + warp_sums[1]) + (warp_sums[2] + warp_sums[3]);
            out[0] = v * (1.0f / (16384.0f * 32.0f));
            g_done_count = 0;   // reset for next graph replay
        }
    }
}

extern "C" void kernel_launch(void* const* d_in, const int* in_sizes, int n_in,
                              void* d_out, int out_size)
{
    const float* fake = (const float*)d_in[0];
    const float* real = (const float*)d_in[1];
    float* out = (float*)d_out;

    lthu_kernel<<<NUM_TILES, 128>>>(fake, real, out);
}

// round 13
// speedup vs baseline: 1.0225x; 1.0225x over previous
#include <cuda_runtime.h>

// FINAL (R8): HBM-roofed streaming reduction for LThuLoss.
//
// Math: thumbnail-mean difference per 128x128 block == sum(fake-real)/16384,
// so the whole loss reduces to |block-sum| accumulation: one pass over 256 MB.
//
// Structure: 32 images * 64 tiles = 2048 tiles; each tile = 4 row-slices
// (32 rows x 128 cols), 8192 slices, one per warp. 1024 CTAs x 8 warps;
// each CTA owns 2 whole tiles. Warp-granular reduce keeps the hot path free
// of CTA barriers; last-CTA epilogue (threadfence + atomic ticket) does a
// fixed-order deterministic final reduce — bit-identical across replays.
//
// Measured 6.25 TB/s. All structural variants (occ 48-89%, MLP 2-8, cache
// policies .ca/.cs/.cg, row-linear vs tiled, grid 1024-8192) pin at
// 6.17-6.26 TB/s -> chip load-path ceiling at NAT clocks; kernel is roofed.
#define NUM_TILES  2048
#define NUM_CTAS   1024
__device__ float g_cta_sums[NUM_CTAS];   // per-CTA: |tile0 sum| + |tile1 sum|
__device__ unsigned int g_done_count = 0;

__global__ void __launch_bounds__(256, 7) lthu_kernel(
    const float* __restrict__ fake, const float* __restrict__ real,
    float* __restrict__ out)
{
    __shared__ float slice_sums[8];   // one per warp
    __shared__ float warp_sums[8];
    __shared__ bool is_last;

    const int lane  = threadIdx.x & 31;
    const int wid   = threadIdx.x >> 5;
    const int slice = blockIdx.x * 8 + wid;   // 0..8191

    const int tile = slice >> 2;              // 0..2047
    const int q    = slice & 3;               // row group q*32 .. q*32+31
    const int b    = tile >> 6;               // image (64 tiles per image)
    const int rem  = tile & 63;
    const int by   = rem >> 3;
    const int bx   = rem & 7;
    const long base = (long)b * (1024 * 1024)
                    + (long)(by * 128 + q * 32) * 1024
                    + (long)bx * 128;

    const float4* f4 = (const float4*)(fake + base) + lane;
    const float4* r4 = (const float4*)(real + base) + lane;
    // slice: 32 rows x 32 float4/row; row stride in float4 units = 256

    float acc = 0.0f;
    #pragma unroll 16
    for (int r = 0; r < 32; ++r) {
        float4 fv = f4[r * 256];
        float4 rv = r4[r * 256];
        acc += (fv.x - rv.x) + (fv.y - rv.y) + (fv.z - rv.z) + (fv.w - rv.w);
    }

    // warp-local reduce — no CTA barrier while other warps stream
    #pragma unroll
    for (int off = 16; off > 0; off >>= 1)
        acc += __shfl_xor_sync(0xFFFFFFFFu, acc, off);

    if (lane == 0)
        slice_sums[wid] = acc;     // signed slice sum, in shared

    __syncthreads();               // single barrier, after all loads complete

    if (threadIdx.x == 0) {
        // CTA owns two complete tiles: slices 0-3 and 4-7
        float t0 = (slice_sums[0] + slice_sums[1]) + (slice_sums[2] + slice_sums[3]);
        float t1 = (slice_sums[4] + slice_sums[5]) + (slice_sums[6] + slice_sums[7]);
        g_cta_sums[blockIdx.x] = fabsf(t0) + fabsf(t1);
        __threadfence();
        unsigned int prev = atomicAdd(&g_done_count, 1u);
        is_last = (prev == NUM_CTAS - 1);
    }
    __syncthreads();

    if (is_last) {
        // fixed-order deterministic reduce of 1024 per-CTA sums
        float s = 0.0f;
        #pragma unroll
        for (int it = 0; it < 4; ++it)
            s += g_cta_sums[threadIdx.x + it * 256];

        #pragma unroll
        for (int off = 16; off > 0; off >>= 1)
            s += __shfl_xor_sync(0xFFFFFFFFu, s, off);
        if (lane == 0) warp_sums[wid] = s;
        __syncthreads();
        if (wid == 0) {
            float v = (lane < 8) ? warp_sums[lane] : 0.0f;
            #pragma unroll
            for (int off = 4; off > 0; off >>= 1)
                v += __shfl_xor_sync(0xFFFFFFFFu, v, off);
            if (lane == 0) {
                out[0] = v * (1.0f / (16384.0f * 32.0f));
                g_done_count = 0;   // reset for next graph replay
            }
        }
    }
}

extern "C" void kernel_launch(void* const* d_in, const int* in_sizes, int n_in,
                              void* d_out, int out_size)
{
    const float* fake = (const float*)d_in[0];
    const float* real = (const float*)d_in[1];
    float* out = (float*)d_out;

    lthu_kernel<<<NUM_CTAS, 256>>>(fake, real, out);
}

// round 14
// speedup vs baseline: 1.0361x; 1.0132x over previous
#include <cuda_runtime.h>

// FINAL (R8): HBM-roofed streaming reduction for LThuLoss.
//
// Math: thumbnail-mean difference per 128x128 block == sum(fake-real)/16384,
// so the whole loss reduces to |block-sum| accumulation: one pass over 256 MB.
//
// Structure: 32 images * 64 tiles = 2048 tiles; each tile = 4 row-slices
// (32 rows x 128 cols), 8192 slices, one per warp. 1024 CTAs x 8 warps;
// each CTA owns 2 whole tiles (SM tile balance 14 max vs 13.84 ideal —
// integer-optimal). Warp-granular reduce keeps the hot path free of CTA
// barriers; last-CTA epilogue (threadfence + atomic ticket) does a
// fixed-order deterministic final reduce — bit-identical across replays.
//
// Measured 6.25 TB/s peak / 6.14-6.25 across runs. All structural variants
// (occ 48-89%, MLP 2-8, .ca/.cs/.cg, row-linear vs tiled, grid 1024-8192,
// 128/256 thr) pin at 6.17-6.26 TB/s -> chip load-path ceiling at NAT
// clocks; kernel is roofed. Best e2e: 43.5 us (floor ~42.5 us).
#define NUM_TILES  2048
#define NUM_CTAS   1024
__device__ float g_cta_sums[NUM_CTAS];   // per-CTA: |tile0 sum| + |tile1 sum|
__device__ unsigned int g_done_count = 0;

__global__ void __launch_bounds__(256, 7) lthu_kernel(
    const float* __restrict__ fake, const float* __restrict__ real,
    float* __restrict__ out)
{
    __shared__ float slice_sums[8];   // one per warp
    __shared__ float warp_sums[8];
    __shared__ bool is_last;

    const int lane  = threadIdx.x & 31;
    const int wid   = threadIdx.x >> 5;
    const int slice = blockIdx.x * 8 + wid;   // 0..8191

    const int tile = slice >> 2;              // 0..2047
    const int q    = slice & 3;               // row group q*32 .. q*32+31
    const int b    = tile >> 6;               // image (64 tiles per image)
    const int rem  = tile & 63;
    const int by   = rem >> 3;
    const int bx   = rem & 7;
    const long base = (long)b * (1024 * 1024)
                    + (long)(by * 128 + q * 32) * 1024
                    + (long)bx * 128;

    const float4* f4 = (const float4*)(fake + base) + lane;
    const float4* r4 = (const float4*)(real + base) + lane;
    // slice: 32 rows x 32 float4/row; row stride in float4 units = 256

    float acc = 0.0f;
    #pragma unroll 16
    for (int r = 0; r < 32; ++r) {
        float4 fv = f4[r * 256];
        float4 rv = r4[r * 256];
        acc += (fv.x - rv.x) + (fv.y - rv.y) + (fv.z - rv.z) + (fv.w - rv.w);
    }

    // warp-local reduce — no CTA barrier while other warps stream
    #pragma unroll
    for (int off = 16; off > 0; off >>= 1)
        acc += __shfl_xor_sync(0xFFFFFFFFu, acc, off);

    if (lane == 0)
        slice_sums[wid] = acc;     // signed slice sum, in shared

    __syncthreads();               // single barrier, after all loads complete

    if (threadIdx.x == 0) {
        // CTA owns two complete tiles: slices 0-3 and 4-7
        float t0 = (slice_sums[0] + slice_sums[1]) + (slice_sums[2] + slice_sums[3]);
        float t1 = (slice_sums[4] + slice_sums[5]) + (slice_sums[6] + slice_sums[7]);
        g_cta_sums[blockIdx.x] = fabsf(t0) + fabsf(t1);
        __threadfence();
        unsigned int prev = atomicAdd(&g_done_count, 1u);
        is_last = (prev == NUM_CTAS - 1);
    }
    __syncthreads();

    if (is_last) {
        // fixed-order deterministic reduce of 1024 per-CTA sums
        float s = 0.0f;
        #pragma unroll
        for (int it = 0; it < 4; ++it)
            s += g_cta_sums[threadIdx.x + it * 256];

        #pragma unroll
        for (int off = 16; off > 0; off >>= 1)
            s += __shfl_xor_sync(0xFFFFFFFFu, s, off);
        if (lane == 0) warp_sums[wid] = s;
        __syncthreads();
        if (wid == 0) {
            float v = (lane < 8) ? warp_sums[lane] : 0.0f;
            #pragma unroll
            for (int off = 4; off > 0; off >>= 1)
                v += __shfl_xor_sync(0xFFFFFFFFu, v, off);
            if (lane == 0) {
                out[0] = v * (1.0f / (16384.0f * 32.0f));
                g_done_count = 0;   // reset for next graph replay
            }
        }
    }
}

extern "C" void kernel_launch(void* const* d_in, const int* in_sizes, int n_in,
                              void* d_out, int out_size)
{
    const float* fake = (const float*)d_in[0];
    const float* real = (const float*)d_in[1];
    float* out = (float*)d_out;

    lthu_kernel<<<NUM_CTAS, 256>>>(fake, real, out);
}